// round 4
// baseline (speedup 1.0000x reference)
#include <cuda_runtime.h>
#include <math.h>

#define HID 128
#define NEG 0.2f
#define MAXN 50000
#define MAXE 800000

// ---------------- static scratch (no allocations allowed) ----------------
__device__ float g_h  [MAXN * HID];
__device__ float g_xl [MAXN * HID];
__device__ float g_xr [MAXN * HID];
__device__ float g_acc[MAXN * HID];
__device__ float g_denom[MAXN];
__device__ float g_deg  [MAXN];
__device__ float g_loop [MAXN * 32];
__device__ int   g_src[MAXE];
__device__ int   g_dst[MAXE];
__device__ int   g_is64;

// ---------------- small helpers ----------------
__device__ __forceinline__ void red4(float* p, float a, float b, float c, float d) {
    asm volatile("red.global.add.v4.f32 [%0], {%1,%2,%3,%4};"
                 :: "l"(p), "f"(a), "f"(b), "f"(c), "f"(d));
}
__device__ __forceinline__ void red1(float* p, float a) {
    asm volatile("red.global.add.f32 [%0], %1;" :: "l"(p), "f"(a));
}
__device__ __forceinline__ float lk(float x) { return x > 0.0f ? x : NEG * x; }

__device__ __forceinline__ unsigned long long pk2(float x, float y) {
    unsigned long long r;
    asm("mov.b64 %0, {%1, %2};" : "=l"(r) : "f"(x), "f"(y));
    return r;
}
__device__ __forceinline__ void fma2(unsigned long long& d,
                                     unsigned long long a, unsigned long long b) {
    asm("fma.rn.f32x2 %0, %1, %2, %0;" : "+l"(d) : "l"(a), "l"(b));
}
__device__ __forceinline__ float2 up2(unsigned long long v) {
    float2 r;
    asm("mov.b64 {%0, %1}, %2;" : "=f"(r.x), "=f"(r.y) : "l"(v));
    return r;
}

// ---------------- dtype detection + index conversion ----------------
__global__ void k_detect(const void* __restrict__ idx, int E, int N) {
    if (threadIdx.x == 0 && blockIdx.x == 0) {
        const long long* p = (const long long*)idx;
        int ok = 1;
        int cnt = 64;
        if (2 * E < 64) cnt = 2 * E;
        for (int i = 0; i < cnt; i++) {
            long long v = p[i];
            if (v < 0 || v >= (long long)N) { ok = 0; break; }
        }
        g_is64 = ok;
    }
}

__global__ void k_prep(const void* __restrict__ idx, int E) {
    int e = blockIdx.x * blockDim.x + threadIdx.x;
    if (e >= E) return;
    if (g_is64) {
        g_src[e] = (int)((const long long*)idx)[e];
        g_dst[e] = (int)((const long long*)idx)[E + e];
    } else {
        g_src[e] = ((const int*)idx)[e];
        g_dst[e] = ((const int*)idx)[E + e];
    }
}

// ---------------- zero (count must be multiple of 4) ----------------
__global__ void k_zero(float4* __restrict__ p, int n4) {
    int i = blockIdx.x * blockDim.x + threadIdx.x;
    if (i < n4) p[i] = make_float4(0.f, 0.f, 0.f, 0.f);
}

// ---------------- self-loop attr accumulation ----------------
__global__ void k_loopacc(const float* __restrict__ ea, int E) {
    int i = blockIdx.x * blockDim.x + threadIdx.x;   // over E*8
    if (i >= E * 8) return;
    int e = i >> 3, j = i & 7;
    int d = g_dst[e];
    float4 v = *(const float4*)(ea + (size_t)e * 32 + j * 4);
    red4(g_loop + (size_t)d * 32 + j * 4, v.x, v.y, v.z, v.w);
    if (j == 0) red1(g_deg + d, 1.0f);
}

__global__ void k_loopnorm(int N) {
    int i = blockIdx.x * blockDim.x + threadIdx.x;   // over N*8
    if (i >= N * 8) return;
    int node = i >> 3;
    float s = 1.0f / fmaxf(g_deg[node], 1.0f);
    float4 v = ((float4*)g_loop)[i];
    v.x *= s; v.y *= s; v.z *= s; v.w *= s;
    ((float4*)g_loop)[i] = v;
}

// ---------------- SGEMM: C[M,128] = A[M,128] @ W[128,128] (+ bias) ----------------
__global__ void __launch_bounds__(256) k_gemm(const float* __restrict__ A,
                                              const float* __restrict__ W,
                                              const float* __restrict__ bias,
                                              float* __restrict__ C, int M) {
    __shared__ float As[8][128];
    __shared__ float Ws[8][128];
    int tid  = threadIdx.x;
    int row0 = blockIdx.x * 128;
    int arow = tid >> 1, acol = (tid & 1) * 4;
    int wrow = tid >> 5, wcol = (tid & 31) * 4;
    int ty = tid >> 4, tx = tid & 15;

    unsigned long long acc2[8][4];
#pragma unroll
    for (int i = 0; i < 8; i++)
#pragma unroll
        for (int j = 0; j < 4; j++) acc2[i][j] = 0ULL;

    for (int k0 = 0; k0 < 128; k0 += 8) {
        int r = row0 + arow;
        float4 av = (r < M) ? *(const float4*)(A + (size_t)r * 128 + k0 + acol)
                            : make_float4(0.f, 0.f, 0.f, 0.f);
        As[acol + 0][arow] = av.x;
        As[acol + 1][arow] = av.y;
        As[acol + 2][arow] = av.z;
        As[acol + 3][arow] = av.w;
        *(float4*)(&Ws[wrow][wcol]) = *(const float4*)(W + (size_t)(k0 + wrow) * 128 + wcol);
        __syncthreads();
#pragma unroll
        for (int kk = 0; kk < 8; kk++) {
            float a[8];
            unsigned long long b2[4];
            *(float4*)(a)     = *(float4*)(&As[kk][ty * 8]);
            *(float4*)(a + 4) = *(float4*)(&As[kk][ty * 8 + 4]);
            const unsigned long long* wp = (const unsigned long long*)(&Ws[kk][tx * 8]);
            b2[0] = wp[0]; b2[1] = wp[1]; b2[2] = wp[2]; b2[3] = wp[3];
#pragma unroll
            for (int i = 0; i < 8; i++) {
                unsigned long long pa = pk2(a[i], a[i]);
#pragma unroll
                for (int j = 0; j < 4; j++) fma2(acc2[i][j], pa, b2[j]);
            }
        }
        __syncthreads();
    }

    float bv[8];
#pragma unroll
    for (int j = 0; j < 8; j++) bv[j] = bias ? bias[tx * 8 + j] : 0.f;

#pragma unroll
    for (int i = 0; i < 8; i++) {
        int r = row0 + ty * 8 + i;
        if (r < M) {
            float2 p0 = up2(acc2[i][0]);
            float2 p1 = up2(acc2[i][1]);
            float2 p2 = up2(acc2[i][2]);
            float2 p3 = up2(acc2[i][3]);
            float4 o0 = make_float4(p0.x + bv[0], p0.y + bv[1],
                                    p1.x + bv[2], p1.y + bv[3]);
            float4 o1 = make_float4(p2.x + bv[4], p2.y + bv[5],
                                    p3.x + bv[6], p3.y + bv[7]);
            *(float4*)(C + (size_t)r * 128 + tx * 8)     = o0;
            *(float4*)(C + (size_t)r * 128 + tx * 8 + 4) = o1;
        }
    }
}

// ---------------- fused edge pass: warp per edge, We in registers ----------------
// Each lane owns 4 output columns (c = lane*4) of We across all 32 k values,
// packed into 64 f32x2 register pairs. ea broadcast via shfl. No ev scratch.
__global__ void __launch_bounds__(128, 3) k_edge(const float* __restrict__ ea,
                                                 const float* __restrict__ We,
                                                 const float* __restrict__ att,
                                                 int E, int T) {
    int lane  = threadIdx.x & 31;
    int gwarp = (blockIdx.x * blockDim.x + threadIdx.x) >> 5;
    int nwarp = (gridDim.x * blockDim.x) >> 5;
    int c = lane * 4;

    // Register-resident We: lane holds We[k][c..c+3] for k=0..31.
    unsigned long long wlo[32], whi[32];
#pragma unroll
    for (int k = 0; k < 32; k++) {
        float4 w = *(const float4*)(We + (size_t)k * HID + c);
        wlo[k] = pk2(w.x, w.y);
        whi[k] = pk2(w.z, w.w);
    }
    float4 at = *(const float4*)(att + c);

    for (int e = gwarp; e < T; e += nwarp) {
        int s, d;
        const float* earow;
        if (e < E) {
            s = g_src[e];
            d = g_dst[e];
            earow = ea + (size_t)e * 32;
        } else {
            s = d = e - E;
            earow = g_loop + (size_t)(e - E) * 32;
        }
        float eav = earow[lane];

        // ev = ea_row @ We (this lane's 4 columns), via shfl broadcast
        unsigned long long e0 = 0ULL, e1 = 0ULL;
#pragma unroll
        for (int k = 0; k < 32; k++) {
            float a = __shfl_sync(0xFFFFFFFFu, eav, k);
            unsigned long long pa = pk2(a, a);
            fma2(e0, pa, wlo[k]);
            fma2(e1, pa, whi[k]);
        }
        float2 v0 = up2(e0), v1 = up2(e1);

        float4 xl = *(const float4*)(g_xl + (size_t)s * HID + c);
        float4 xr = *(const float4*)(g_xr + (size_t)d * HID + c);

        float p = lk(xl.x + xr.x + v0.x) * at.x
                + lk(xl.y + xr.y + v0.y) * at.y
                + lk(xl.z + xr.z + v1.x) * at.z
                + lk(xl.w + xr.w + v1.y) * at.w;
#pragma unroll
        for (int o = 16; o; o >>= 1) p += __shfl_xor_sync(0xFFFFFFFFu, p, o);

        float ez = __expf(p);
        red4(g_acc + (size_t)d * HID + c, ez * xl.x, ez * xl.y, ez * xl.z, ez * xl.w);
        if (lane == 0) red1(g_denom + d, ez);
    }
}

// ---------------- normalize + bias + silu ----------------
__global__ void k_norm(const float* __restrict__ bo, float* __restrict__ out, int N) {
    int i = blockIdx.x * blockDim.x + threadIdx.x;   // over N*32 float4s
    if (i >= N * 32) return;
    int node = i >> 5;
    int c = (i & 31) * 4;
    float inv = 1.0f / g_denom[node];
    float4 a = *(float4*)(g_acc + (size_t)node * HID + c);
    float4 b = *(const float4*)(bo + c);
    float vx = a.x * inv + b.x;
    float vy = a.y * inv + b.y;
    float vz = a.z * inv + b.z;
    float vw = a.w * inv + b.w;
    float4 o;
    o.x = vx / (1.0f + __expf(-vx));
    o.y = vy / (1.0f + __expf(-vy));
    o.z = vz / (1.0f + __expf(-vz));
    o.w = vw / (1.0f + __expf(-vw));
    *(float4*)(out + (size_t)node * HID + c) = o;
}

// ---------------- host orchestration ----------------
static inline void zero_f(float* p, int count) {          // count % 4 == 0
    int n4 = count >> 2;
    k_zero<<<(n4 + 255) / 256, 256>>>((float4*)p, n4);
}

extern "C" void kernel_launch(void* const* d_in, const int* in_sizes, int n_in,
                              void* d_out, int out_size) {
    const float* x    = (const float*)d_in[0];
    const void*  eidx = d_in[1];
    const float* ea   = (const float*)d_in[2];
    const float* W_emb = (const float*)d_in[3];
    const float* b_emb = (const float*)d_in[4];
    const float* Wl[2]  = {(const float*)d_in[5],  (const float*)d_in[11]};
    const float* bl[2]  = {(const float*)d_in[6],  (const float*)d_in[12]};
    const float* Wr[2]  = {(const float*)d_in[7],  (const float*)d_in[13]};
    const float* We[2]  = {(const float*)d_in[8],  (const float*)d_in[14]};
    const float* att[2] = {(const float*)d_in[9],  (const float*)d_in[15]};
    const float* bo[2]  = {(const float*)d_in[10], (const float*)d_in[16]};

    int N = in_sizes[0] / HID;
    int E = in_sizes[2] / 32;
    int T = E + N;

    float *p_h, *p_xl, *p_xr, *p_acc, *p_denom, *p_deg, *p_loop;
    cudaGetSymbolAddress((void**)&p_h,     g_h);
    cudaGetSymbolAddress((void**)&p_xl,    g_xl);
    cudaGetSymbolAddress((void**)&p_xr,    g_xr);
    cudaGetSymbolAddress((void**)&p_acc,   g_acc);
    cudaGetSymbolAddress((void**)&p_denom, g_denom);
    cudaGetSymbolAddress((void**)&p_deg,   g_deg);
    cudaGetSymbolAddress((void**)&p_loop,  g_loop);

    k_detect<<<1, 1>>>(eidx, E, N);
    k_prep<<<(E + 255) / 256, 256>>>(eidx, E);

    // self-loop attr (layer-independent)
    zero_f(p_deg, N);
    zero_f(p_loop, N * 32);
    k_loopacc<<<(E * 8 + 255) / 256, 256>>>(ea, E);
    k_loopnorm<<<(N * 8 + 255) / 256, 256>>>(N);

    // embedding
    int gb_n = (N + 127) / 128;
    k_gemm<<<gb_n, 256>>>(x, W_emb, b_emb, p_h, N);

    // fixed grid for the fused edge kernel: grid-stride over edges
    int edge_blocks = 1776;   // 148 SMs * 3 blocks * (fits any larger SM count too)

    for (int l = 0; l < 2; l++) {
        k_gemm<<<gb_n, 256>>>(p_h, Wl[l], bl[l], p_xl, N);
        k_gemm<<<gb_n, 256>>>(p_h, Wr[l], nullptr, p_xr, N);

        zero_f(p_acc, N * HID);
        zero_f(p_denom, N);
        k_edge<<<edge_blocks, 128>>>(ea, We[l], att[l], E, T);

        float* dst = (l == 0) ? p_h : (float*)d_out;
        k_norm<<<(N * 32 + 255) / 256, 256>>>(bo[l], dst, N);
    }
}

// round 6
// speedup vs baseline: 1.1095x; 1.1095x over previous
#include <cuda_runtime.h>
#include <math.h>

#define HID 128
#define NEG 0.2f
#define MAXN 50000
#define MAXE 800000

// ---------------- static scratch (no allocations allowed) ----------------
__device__ float g_h  [MAXN * HID];
__device__ float g_xl [MAXN * HID];
__device__ float g_xr [MAXN * HID];
__device__ float g_acc[MAXN * HID];
__device__ float g_denom[MAXN];
__device__ float g_deg  [MAXN];
__device__ float g_loop [MAXN * 32];
__device__ int   g_src[MAXE];
__device__ int   g_dst[MAXE];
__device__ int   g_is64;

// ---------------- small helpers ----------------
__device__ __forceinline__ void red4(float* p, float a, float b, float c, float d) {
    asm volatile("red.global.add.v4.f32 [%0], {%1,%2,%3,%4};"
                 :: "l"(p), "f"(a), "f"(b), "f"(c), "f"(d));
}
__device__ __forceinline__ void red1(float* p, float a) {
    asm volatile("red.global.add.f32 [%0], %1;" :: "l"(p), "f"(a));
}
__device__ __forceinline__ float lk(float x) { return x > 0.0f ? x : NEG * x; }

__device__ __forceinline__ unsigned long long pk2(float x, float y) {
    unsigned long long r;
    asm("mov.b64 %0, {%1, %2};" : "=l"(r) : "f"(x), "f"(y));
    return r;
}
__device__ __forceinline__ void fma2(unsigned long long& d,
                                     unsigned long long a, unsigned long long b) {
    asm("fma.rn.f32x2 %0, %1, %2, %0;" : "+l"(d) : "l"(a), "l"(b));
}
__device__ __forceinline__ float2 up2(unsigned long long v) {
    float2 r;
    asm("mov.b64 {%0, %1}, %2;" : "=f"(r.x), "=f"(r.y) : "l"(v));
    return r;
}

// ---------------- dtype detection + index conversion ----------------
__global__ void k_detect(const void* __restrict__ idx, int E, int N) {
    if (threadIdx.x == 0 && blockIdx.x == 0) {
        const long long* p = (const long long*)idx;
        int ok = 1;
        int cnt = 64;
        if (2 * E < 64) cnt = 2 * E;
        for (int i = 0; i < cnt; i++) {
            long long v = p[i];
            if (v < 0 || v >= (long long)N) { ok = 0; break; }
        }
        g_is64 = ok;
    }
}

__global__ void k_prep(const void* __restrict__ idx, int E) {
    int e = blockIdx.x * blockDim.x + threadIdx.x;
    if (e >= E) return;
    if (g_is64) {
        g_src[e] = (int)((const long long*)idx)[e];
        g_dst[e] = (int)((const long long*)idx)[E + e];
    } else {
        g_src[e] = ((const int*)idx)[e];
        g_dst[e] = ((const int*)idx)[E + e];
    }
}

// ---------------- zero helpers ----------------
// zero deg[N] and loop[N*32] in one launch
__global__ void k_zero_dl(int N) {
    int i = blockIdx.x * blockDim.x + threadIdx.x;
    int n4deg = N >> 2, n4loop = N * 8;
    if (i < n4deg) ((float4*)g_deg)[i] = make_float4(0.f, 0.f, 0.f, 0.f);
    if (i < n4loop) ((float4*)g_loop)[i] = make_float4(0.f, 0.f, 0.f, 0.f);
}
// zero acc[N*128] and denom[N]
__global__ void k_zero_ad(int N) {
    int i = blockIdx.x * blockDim.x + threadIdx.x;
    int n4acc = N * 32, n4den = N >> 2;
    if (i < n4acc) ((float4*)g_acc)[i] = make_float4(0.f, 0.f, 0.f, 0.f);
    if (i < n4den) ((float4*)g_denom)[i] = make_float4(0.f, 0.f, 0.f, 0.f);
}

// ---------------- self-loop attr accumulation ----------------
__global__ void k_loopacc(const float* __restrict__ ea, int E) {
    int i = blockIdx.x * blockDim.x + threadIdx.x;   // over E*8
    if (i >= E * 8) return;
    int e = i >> 3, j = i & 7;
    int d = g_dst[e];
    float4 v = *(const float4*)(ea + (size_t)e * 32 + j * 4);
    red4(g_loop + (size_t)d * 32 + j * 4, v.x, v.y, v.z, v.w);
    if (j == 0) red1(g_deg + d, 1.0f);
}

__global__ void k_loopnorm(int N) {
    int i = blockIdx.x * blockDim.x + threadIdx.x;   // over N*8
    if (i >= N * 8) return;
    int node = i >> 3;
    float s = 1.0f / fmaxf(g_deg[node], 1.0f);
    float4 v = ((float4*)g_loop)[i];
    v.x *= s; v.y *= s; v.z *= s; v.w *= s;
    ((float4*)g_loop)[i] = v;
}

// ---------------- SGEMM: C[M,128] = A[M,128] @ W[128,128] (+ bias) ----------------
__global__ void __launch_bounds__(256) k_gemm(const float* __restrict__ A,
                                              const float* __restrict__ W,
                                              const float* __restrict__ bias,
                                              float* __restrict__ C, int M) {
    __shared__ float As[8][128];
    __shared__ float Ws[8][128];
    int tid  = threadIdx.x;
    int row0 = blockIdx.x * 128;
    int arow = tid >> 1, acol = (tid & 1) * 4;
    int wrow = tid >> 5, wcol = (tid & 31) * 4;
    int ty = tid >> 4, tx = tid & 15;

    unsigned long long acc2[8][4];
#pragma unroll
    for (int i = 0; i < 8; i++)
#pragma unroll
        for (int j = 0; j < 4; j++) acc2[i][j] = 0ULL;

    for (int k0 = 0; k0 < 128; k0 += 8) {
        int r = row0 + arow;
        float4 av = (r < M) ? *(const float4*)(A + (size_t)r * 128 + k0 + acol)
                            : make_float4(0.f, 0.f, 0.f, 0.f);
        As[acol + 0][arow] = av.x;
        As[acol + 1][arow] = av.y;
        As[acol + 2][arow] = av.z;
        As[acol + 3][arow] = av.w;
        *(float4*)(&Ws[wrow][wcol]) = *(const float4*)(W + (size_t)(k0 + wrow) * 128 + wcol);
        __syncthreads();
#pragma unroll
        for (int kk = 0; kk < 8; kk++) {
            float a[8];
            unsigned long long b2[4];
            *(float4*)(a)     = *(float4*)(&As[kk][ty * 8]);
            *(float4*)(a + 4) = *(float4*)(&As[kk][ty * 8 + 4]);
            const unsigned long long* wp = (const unsigned long long*)(&Ws[kk][tx * 8]);
            b2[0] = wp[0]; b2[1] = wp[1]; b2[2] = wp[2]; b2[3] = wp[3];
#pragma unroll
            for (int i = 0; i < 8; i++) {
                unsigned long long pa = pk2(a[i], a[i]);
#pragma unroll
                for (int j = 0; j < 4; j++) fma2(acc2[i][j], pa, b2[j]);
            }
        }
        __syncthreads();
    }

    float bv[8];
#pragma unroll
    for (int j = 0; j < 8; j++) bv[j] = bias ? bias[tx * 8 + j] : 0.f;

#pragma unroll
    for (int i = 0; i < 8; i++) {
        int r = row0 + ty * 8 + i;
        if (r < M) {
            float2 p0 = up2(acc2[i][0]);
            float2 p1 = up2(acc2[i][1]);
            float2 p2 = up2(acc2[i][2]);
            float2 p3 = up2(acc2[i][3]);
            float4 o0 = make_float4(p0.x + bv[0], p0.y + bv[1],
                                    p1.x + bv[2], p1.y + bv[3]);
            float4 o1 = make_float4(p2.x + bv[4], p2.y + bv[5],
                                    p3.x + bv[6], p3.y + bv[7]);
            *(float4*)(C + (size_t)r * 128 + tx * 8)     = o0;
            *(float4*)(C + (size_t)r * 128 + tx * 8 + 4) = o1;
        }
    }
}

// ---------------- fused edge GEMM + score + aggregate ----------------
// One block = 128 edges. ev = ea_tile @ We via smem-tiled FFMA2 GEMM (K=32),
// then fused epilogue: gather xl/xr, leaky+att logit, exp, red atomics.
__global__ void __launch_bounds__(256) k_escore(const float* __restrict__ ea,
                                                const float* __restrict__ We,
                                                const float* __restrict__ att,
                                                int E, int T) {
    __shared__ float As[32][128];    // [k][edge-row]
    __shared__ float Ws[32][128];    // [k][col]
    __shared__ int   ssrc[128], sdst[128];
    __shared__ float sp[128][17];    // per-row logit partials (stride 17: conflict-free)
    __shared__ float sez[128];

    int tid = threadIdx.x;
    int e0  = blockIdx.x * 128;
    int ty = tid >> 4, tx = tid & 15;

    // Load We (32x128, row-major) straight into Ws
    {
        const float4* src = (const float4*)We;
        float4* dstp = (float4*)&Ws[0][0];
#pragma unroll
        for (int q = 0; q < 4; q++) dstp[tid + q * 256] = src[tid + q * 256];
    }
    // Load src/dst (self-loop rows map to node ids)
    if (tid < 128) {
        int e = e0 + tid;
        if (e < E)      { ssrc[tid] = g_src[e]; sdst[tid] = g_dst[e]; }
        else if (e < T) { ssrc[tid] = sdst[tid] = e - E; }
        else            { ssrc[tid] = sdst[tid] = 0; }
    }
    // Load ea tile transposed: 2 threads/row, each covers 16 k values
    {
        int arow = tid >> 1;
        int kb   = (tid & 1) * 16;
        int e    = e0 + arow;
        const float* rowp = (e < E) ? (ea + (size_t)e * 32)
                          : (e < T) ? (g_loop + (size_t)(e - E) * 32)
                                    : (const float*)0;
#pragma unroll
        for (int q = 0; q < 4; q++) {
            float4 v = rowp ? *(const float4*)(rowp + kb + q * 4)
                            : make_float4(0.f, 0.f, 0.f, 0.f);
            As[kb + q * 4 + 0][arow] = v.x;
            As[kb + q * 4 + 1][arow] = v.y;
            As[kb + q * 4 + 2][arow] = v.z;
            As[kb + q * 4 + 3][arow] = v.w;
        }
    }
    __syncthreads();

    // ev GEMM: 8 rows x 8 cols per thread, K=32
    unsigned long long acc2[8][4];
#pragma unroll
    for (int i = 0; i < 8; i++)
#pragma unroll
        for (int j = 0; j < 4; j++) acc2[i][j] = 0ULL;

#pragma unroll
    for (int k = 0; k < 32; k++) {
        float a[8];
        unsigned long long b2[4];
        *(float4*)(a)     = *(float4*)(&As[k][ty * 8]);
        *(float4*)(a + 4) = *(float4*)(&As[k][ty * 8 + 4]);
        const unsigned long long* wp = (const unsigned long long*)(&Ws[k][tx * 8]);
        b2[0] = wp[0]; b2[1] = wp[1]; b2[2] = wp[2]; b2[3] = wp[3];
#pragma unroll
        for (int i = 0; i < 8; i++) {
            unsigned long long pa = pk2(a[i], a[i]);
#pragma unroll
            for (int j = 0; j < 4; j++) fma2(acc2[i][j], pa, b2[j]);
        }
    }

    // Epilogue 1: per-(row, tx) logit partials; keep xl live for epilogue 2
    float4 at0 = *(const float4*)(att + tx * 8);
    float4 at1 = *(const float4*)(att + tx * 8 + 4);
    float4 xl0r[8], xl1r[8];
#pragma unroll
    for (int i = 0; i < 8; i++) {
        int r = ty * 8 + i;
        int s = ssrc[r], d = sdst[r];
        const float* xlp = g_xl + (size_t)s * HID + tx * 8;
        const float* xrp = g_xr + (size_t)d * HID + tx * 8;
        float4 xl0 = *(const float4*)(xlp);
        float4 xl1 = *(const float4*)(xlp + 4);
        float4 xr0 = *(const float4*)(xrp);
        float4 xr1 = *(const float4*)(xrp + 4);
        xl0r[i] = xl0; xl1r[i] = xl1;
        float2 v0 = up2(acc2[i][0]);
        float2 v1 = up2(acc2[i][1]);
        float2 v2 = up2(acc2[i][2]);
        float2 v3 = up2(acc2[i][3]);
        float p = lk(xl0.x + xr0.x + v0.x) * at0.x
                + lk(xl0.y + xr0.y + v0.y) * at0.y
                + lk(xl0.z + xr0.z + v1.x) * at0.z
                + lk(xl0.w + xr0.w + v1.y) * at0.w
                + lk(xl1.x + xr1.x + v2.x) * at1.x
                + lk(xl1.y + xr1.y + v2.y) * at1.y
                + lk(xl1.z + xr1.z + v3.x) * at1.z
                + lk(xl1.w + xr1.w + v3.y) * at1.w;
        sp[r][tx] = p;
    }
    __syncthreads();

    // Reduce 16 partials per row -> ez; denominator atomic
    if (tid < 128) {
        float sum = 0.f;
#pragma unroll
        for (int j = 0; j < 16; j++) sum += sp[tid][j];
        float ez = __expf(sum);
        sez[tid] = ez;
        int e = e0 + tid;
        if (e < T) red1(&g_denom[sdst[tid]], ez);
    }
    __syncthreads();

    // Epilogue 2: numerator atomics from register-resident xl
#pragma unroll
    for (int i = 0; i < 8; i++) {
        int r = ty * 8 + i;
        int e = e0 + r;
        if (e >= T) continue;
        int d = sdst[r];
        float ez = sez[r];
        float4 xl0 = xl0r[i], xl1 = xl1r[i];
        float* ap = g_acc + (size_t)d * HID + tx * 8;
        red4(ap,     ez * xl0.x, ez * xl0.y, ez * xl0.z, ez * xl0.w);
        red4(ap + 4, ez * xl1.x, ez * xl1.y, ez * xl1.z, ez * xl1.w);
    }
}

// ---------------- normalize + bias + silu ----------------
__global__ void k_norm(const float* __restrict__ bo, float* __restrict__ out, int N) {
    int i = blockIdx.x * blockDim.x + threadIdx.x;   // over N*32 float4s
    if (i >= N * 32) return;
    int node = i >> 5;
    int c = (i & 31) * 4;
    float inv = 1.0f / g_denom[node];
    float4 a = *(float4*)(g_acc + (size_t)node * HID + c);
    float4 b = *(const float4*)(bo + c);
    float vx = a.x * inv + b.x;
    float vy = a.y * inv + b.y;
    float vz = a.z * inv + b.z;
    float vw = a.w * inv + b.w;
    float4 o;
    o.x = vx / (1.0f + __expf(-vx));
    o.y = vy / (1.0f + __expf(-vy));
    o.z = vz / (1.0f + __expf(-vz));
    o.w = vw / (1.0f + __expf(-vw));
    *(float4*)(out + (size_t)node * HID + c) = o;
}

// ---------------- host orchestration ----------------
extern "C" void kernel_launch(void* const* d_in, const int* in_sizes, int n_in,
                              void* d_out, int out_size) {
    const float* x    = (const float*)d_in[0];
    const void*  eidx = d_in[1];
    const float* ea   = (const float*)d_in[2];
    const float* W_emb = (const float*)d_in[3];
    const float* b_emb = (const float*)d_in[4];
    const float* Wl[2]  = {(const float*)d_in[5],  (const float*)d_in[11]};
    const float* bl[2]  = {(const float*)d_in[6],  (const float*)d_in[12]};
    const float* Wr[2]  = {(const float*)d_in[7],  (const float*)d_in[13]};
    const float* We[2]  = {(const float*)d_in[8],  (const float*)d_in[14]};
    const float* att[2] = {(const float*)d_in[9],  (const float*)d_in[15]};
    const float* bo[2]  = {(const float*)d_in[10], (const float*)d_in[16]};

    int N = in_sizes[0] / HID;
    int E = in_sizes[2] / 32;
    int T = E + N;

    float *p_h;
    cudaGetSymbolAddress((void**)&p_h, g_h);

    // launch order keeps ncu -s 5 on the embedding GEMM
    k_detect<<<1, 1>>>(eidx, E, N);                                  // 1
    k_prep<<<(E + 255) / 256, 256>>>(eidx, E);                       // 2
    k_zero_dl<<<(N * 8 + 255) / 256, 256>>>(N);                      // 3
    k_loopacc<<<(E * 8 + 255) / 256, 256>>>(ea, E);                  // 4

    int gb_n = (N + 127) / 128;
    k_gemm<<<gb_n, 256>>>(x, W_emb, b_emb, p_h, N);                  // 5 <- profiled

    k_loopnorm<<<(N * 8 + 255) / 256, 256>>>(N);                     // 6

    float *p_xl, *p_xr;
    cudaGetSymbolAddress((void**)&p_xl, g_xl);
    cudaGetSymbolAddress((void**)&p_xr, g_xr);

    int eb = (T + 127) / 128;
    for (int l = 0; l < 2; l++) {
        k_gemm<<<gb_n, 256>>>(p_h, Wl[l], bl[l], p_xl, N);
        k_gemm<<<gb_n, 256>>>(p_h, Wr[l], nullptr, p_xr, N);
        k_zero_ad<<<(N * 32 + 255) / 256, 256>>>(N);
        k_escore<<<eb, 256>>>(ea, We[l], att[l], E, T);
        float* dst = (l == 0) ? p_h : (float*)d_out;
        k_norm<<<(N * 32 + 255) / 256, 256>>>(bo[l], dst, N);
    }
}

// round 7
// speedup vs baseline: 1.7038x; 1.5357x over previous
#include <cuda_runtime.h>
#include <math.h>

#define HID 128
#define NEG 0.2f
#define MAXN 50000
#define MAXE 800000

// ---------------- static scratch (no allocations allowed) ----------------
__device__ float g_h  [MAXN * HID];
__device__ float g_xl [MAXN * HID];
__device__ float g_xr [MAXN * HID];
__device__ float g_acc[MAXN * HID];
__device__ float g_denom[MAXN];
__device__ float g_deg  [MAXN];
__device__ float g_loop [MAXN * 32];
__device__ int   g_src[MAXE];
__device__ int   g_dst[MAXE];
__device__ int   g_is64;

// ---------------- small helpers ----------------
__device__ __forceinline__ void red4(float* p, float a, float b, float c, float d) {
    asm volatile("red.global.add.v4.f32 [%0], {%1,%2,%3,%4};"
                 :: "l"(p), "f"(a), "f"(b), "f"(c), "f"(d));
}
__device__ __forceinline__ void red1(float* p, float a) {
    asm volatile("red.global.add.f32 [%0], %1;" :: "l"(p), "f"(a));
}
__device__ __forceinline__ float lk(float x) { return x > 0.0f ? x : NEG * x; }

__device__ __forceinline__ unsigned long long pk2(float x, float y) {
    unsigned long long r;
    asm("mov.b64 %0, {%1, %2};" : "=l"(r) : "f"(x), "f"(y));
    return r;
}
__device__ __forceinline__ void fma2(unsigned long long& d,
                                     unsigned long long a, unsigned long long b) {
    asm("fma.rn.f32x2 %0, %1, %2, %0;" : "+l"(d) : "l"(a), "l"(b));
}
__device__ __forceinline__ float2 up2(unsigned long long v) {
    float2 r;
    asm("mov.b64 {%0, %1}, %2;" : "=f"(r.x), "=f"(r.y) : "l"(v));
    return r;
}
__device__ __forceinline__ unsigned int tf32b(float x) {
    unsigned int r;
    asm("cvt.rna.tf32.f32 %0, %1;" : "=r"(r) : "f"(x));
    return r;
}
__device__ __forceinline__ void mma_tf32(float* d, const unsigned int* a,
                                         unsigned int b0, unsigned int b1) {
    asm("mma.sync.aligned.m16n8k8.row.col.f32.tf32.tf32.f32 "
        "{%0,%1,%2,%3}, {%4,%5,%6,%7}, {%8,%9}, {%0,%1,%2,%3};"
        : "+f"(d[0]), "+f"(d[1]), "+f"(d[2]), "+f"(d[3])
        : "r"(a[0]), "r"(a[1]), "r"(a[2]), "r"(a[3]), "r"(b0), "r"(b1));
}

// ---------------- dtype detection + index conversion ----------------
__global__ void k_detect(const void* __restrict__ idx, int E, int N) {
    if (threadIdx.x == 0 && blockIdx.x == 0) {
        const long long* p = (const long long*)idx;
        int ok = 1;
        int cnt = 64;
        if (2 * E < 64) cnt = 2 * E;
        for (int i = 0; i < cnt; i++) {
            long long v = p[i];
            if (v < 0 || v >= (long long)N) { ok = 0; break; }
        }
        g_is64 = ok;
    }
}

__global__ void k_prep(const void* __restrict__ idx, int E) {
    int e = blockIdx.x * blockDim.x + threadIdx.x;
    if (e >= E) return;
    if (g_is64) {
        g_src[e] = (int)((const long long*)idx)[e];
        g_dst[e] = (int)((const long long*)idx)[E + e];
    } else {
        g_src[e] = ((const int*)idx)[e];
        g_dst[e] = ((const int*)idx)[E + e];
    }
}

// ---------------- zero helpers ----------------
__global__ void k_zero_dl(int N) {
    int i = blockIdx.x * blockDim.x + threadIdx.x;
    int n4deg = N >> 2, n4loop = N * 8;
    if (i < n4deg) ((float4*)g_deg)[i] = make_float4(0.f, 0.f, 0.f, 0.f);
    if (i < n4loop) ((float4*)g_loop)[i] = make_float4(0.f, 0.f, 0.f, 0.f);
}
__global__ void k_zero_ad(int N) {
    int i = blockIdx.x * blockDim.x + threadIdx.x;
    int n4acc = N * 32, n4den = N >> 2;
    if (i < n4acc) ((float4*)g_acc)[i] = make_float4(0.f, 0.f, 0.f, 0.f);
    if (i < n4den) ((float4*)g_denom)[i] = make_float4(0.f, 0.f, 0.f, 0.f);
}

// ---------------- self-loop attr accumulation ----------------
__global__ void k_loopacc(const float* __restrict__ ea, int E) {
    int i = blockIdx.x * blockDim.x + threadIdx.x;   // over E*8
    if (i >= E * 8) return;
    int e = i >> 3, j = i & 7;
    int d = g_dst[e];
    float4 v = *(const float4*)(ea + (size_t)e * 32 + j * 4);
    red4(g_loop + (size_t)d * 32 + j * 4, v.x, v.y, v.z, v.w);
    if (j == 0) red1(g_deg + d, 1.0f);
}

__global__ void k_loopnorm(int N) {
    int i = blockIdx.x * blockDim.x + threadIdx.x;   // over N*8
    if (i >= N * 8) return;
    int node = i >> 3;
    float s = 1.0f / fmaxf(g_deg[node], 1.0f);
    float4 v = ((float4*)g_loop)[i];
    v.x *= s; v.y *= s; v.z *= s; v.w *= s;
    ((float4*)g_loop)[i] = v;
}

// ---------------- tf32 tensor-core GEMM: C[M,128] = A[M,128] @ W[128,128] (+bias) ----
// 128x128 block tile, 8 warps (warp tile 32x64), K chunked by 32,
// mma.sync.m16n8k8 tf32, fp32 accumulate.
__global__ void __launch_bounds__(256) k_gemm_tc(const float* __restrict__ A,
                                                 const float* __restrict__ W,
                                                 const float* __restrict__ bias,
                                                 float* __restrict__ C, int M) {
    __shared__ float As[128][36];   // tf32 bit patterns, padded (bank-conflict-free reads)
    __shared__ float Ws[32][136];   // tf32 bit patterns, padded
    int tid  = threadIdx.x;
    int warp = tid >> 5, lane = tid & 31;
    int gid = lane >> 2, tig = lane & 3;
    int wr = warp & 3, wc = warp >> 2;        // warp tile origin: (wr*32, wc*64)
    int row0 = blockIdx.x * 128;

    float acc[2][8][4];
#pragma unroll
    for (int ar = 0; ar < 2; ar++)
#pragma unroll
        for (int ac = 0; ac < 8; ac++)
#pragma unroll
            for (int q = 0; q < 4; q++) acc[ar][ac][q] = 0.f;

    for (int kc = 0; kc < 128; kc += 32) {
        // A chunk 128x32 -> As (2 threads/row, 16 cols each)
        {
            int r  = tid >> 1;
            int k4 = (tid & 1) * 16;
            bool ok = (row0 + r) < M;
            const float* ap = A + (size_t)(row0 + r) * 128 + kc + k4;
#pragma unroll
            for (int q = 0; q < 4; q++) {
                float4 v = ok ? *(const float4*)(ap + q * 4)
                              : make_float4(0.f, 0.f, 0.f, 0.f);
                float4 t;
                t.x = __uint_as_float(tf32b(v.x));
                t.y = __uint_as_float(tf32b(v.y));
                t.z = __uint_as_float(tf32b(v.z));
                t.w = __uint_as_float(tf32b(v.w));
                *(float4*)(&As[r][k4 + q * 4]) = t;
            }
        }
        // W chunk 32x128 -> Ws (8 threads/row, 16 cols each)
        {
            int r  = tid >> 3;
            int c4 = (tid & 7) * 16;
            const float* wp = W + (size_t)(kc + r) * 128 + c4;
#pragma unroll
            for (int q = 0; q < 4; q++) {
                float4 v = *(const float4*)(wp + q * 4);
                float4 t;
                t.x = __uint_as_float(tf32b(v.x));
                t.y = __uint_as_float(tf32b(v.y));
                t.z = __uint_as_float(tf32b(v.z));
                t.w = __uint_as_float(tf32b(v.w));
                *(float4*)(&Ws[r][c4 + q * 4]) = t;
            }
        }
        __syncthreads();

#pragma unroll
        for (int ks = 0; ks < 4; ks++) {
            int k0 = ks * 8;
            unsigned int af[2][4];
#pragma unroll
            for (int ar = 0; ar < 2; ar++) {
                int rb = wr * 32 + ar * 16;
                af[ar][0] = __float_as_uint(As[rb + gid    ][k0 + tig]);
                af[ar][1] = __float_as_uint(As[rb + gid + 8][k0 + tig]);
                af[ar][2] = __float_as_uint(As[rb + gid    ][k0 + tig + 4]);
                af[ar][3] = __float_as_uint(As[rb + gid + 8][k0 + tig + 4]);
            }
#pragma unroll
            for (int ac = 0; ac < 8; ac++) {
                int cb = wc * 64 + ac * 8;
                unsigned int b0 = __float_as_uint(Ws[k0 + tig    ][cb + gid]);
                unsigned int b1 = __float_as_uint(Ws[k0 + tig + 4][cb + gid]);
                mma_tf32(acc[0][ac], af[0], b0, b1);
                mma_tf32(acc[1][ac], af[1], b0, b1);
            }
        }
        __syncthreads();
    }

    // epilogue
#pragma unroll
    for (int ar = 0; ar < 2; ar++) {
        int rb = row0 + wr * 32 + ar * 16;
#pragma unroll
        for (int ac = 0; ac < 8; ac++) {
            int col = wc * 64 + ac * 8 + 2 * tig;
            float b0v = bias ? bias[col]     : 0.f;
            float b1v = bias ? bias[col + 1] : 0.f;
            int r0 = rb + gid, r1 = rb + gid + 8;
            if (r0 < M) {
                float2 v = make_float2(acc[ar][ac][0] + b0v, acc[ar][ac][1] + b1v);
                *(float2*)(C + (size_t)r0 * 128 + col) = v;
            }
            if (r1 < M) {
                float2 v = make_float2(acc[ar][ac][2] + b0v, acc[ar][ac][3] + b1v);
                *(float2*)(C + (size_t)r1 * 128 + col) = v;
            }
        }
    }
}

// ---------------- fused edge GEMM + score + aggregate ----------------
// One block = 128 edges. ev = ea_tile @ We via smem-tiled FFMA2 GEMM (K=32),
// then fused epilogue: gather xl/xr, leaky+att logit, exp, red atomics.
// launch_bounds(256,2): keep regs <=128 so 2 blocks/SM hide gather latency.
__global__ void __launch_bounds__(256, 2) k_escore(const float* __restrict__ ea,
                                                   const float* __restrict__ We,
                                                   const float* __restrict__ att,
                                                   int E, int T) {
    __shared__ float As[32][128];    // [k][edge-row]
    __shared__ float Ws[32][128];    // [k][col]
    __shared__ int   ssrc[128], sdst[128];
    __shared__ float sp[128][17];    // per-row logit partials (stride 17: conflict-free)
    __shared__ float sez[128];

    int tid = threadIdx.x;
    int e0  = blockIdx.x * 128;
    int ty = tid >> 4, tx = tid & 15;

    // Load We (32x128, row-major) straight into Ws
    {
        const float4* src = (const float4*)We;
        float4* dstp = (float4*)&Ws[0][0];
#pragma unroll
        for (int q = 0; q < 4; q++) dstp[tid + q * 256] = src[tid + q * 256];
    }
    // Load src/dst (self-loop rows map to node ids)
    if (tid < 128) {
        int e = e0 + tid;
        if (e < E)      { ssrc[tid] = g_src[e]; sdst[tid] = g_dst[e]; }
        else if (e < T) { ssrc[tid] = sdst[tid] = e - E; }
        else            { ssrc[tid] = sdst[tid] = 0; }
    }
    // Load ea tile transposed: 2 threads/row, each covers 16 k values
    {
        int arow = tid >> 1;
        int kb   = (tid & 1) * 16;
        int e    = e0 + arow;
        const float* rowp = (e < E) ? (ea + (size_t)e * 32)
                          : (e < T) ? (g_loop + (size_t)(e - E) * 32)
                                    : (const float*)0;
#pragma unroll
        for (int q = 0; q < 4; q++) {
            float4 v = rowp ? *(const float4*)(rowp + kb + q * 4)
                            : make_float4(0.f, 0.f, 0.f, 0.f);
            As[kb + q * 4 + 0][arow] = v.x;
            As[kb + q * 4 + 1][arow] = v.y;
            As[kb + q * 4 + 2][arow] = v.z;
            As[kb + q * 4 + 3][arow] = v.w;
        }
    }
    __syncthreads();

    // ev GEMM: 8 rows x 8 cols per thread, K=32
    unsigned long long acc2[8][4];
#pragma unroll
    for (int i = 0; i < 8; i++)
#pragma unroll
        for (int j = 0; j < 4; j++) acc2[i][j] = 0ULL;

#pragma unroll
    for (int k = 0; k < 32; k++) {
        float a[8];
        unsigned long long b2[4];
        *(float4*)(a)     = *(float4*)(&As[k][ty * 8]);
        *(float4*)(a + 4) = *(float4*)(&As[k][ty * 8 + 4]);
        const unsigned long long* wp = (const unsigned long long*)(&Ws[k][tx * 8]);
        b2[0] = wp[0]; b2[1] = wp[1]; b2[2] = wp[2]; b2[3] = wp[3];
#pragma unroll
        for (int i = 0; i < 8; i++) {
            unsigned long long pa = pk2(a[i], a[i]);
#pragma unroll
            for (int j = 0; j < 4; j++) fma2(acc2[i][j], pa, b2[j]);
        }
    }

    // Epilogue 1: per-(row, tx) logit partials
    float4 at0 = *(const float4*)(att + tx * 8);
    float4 at1 = *(const float4*)(att + tx * 8 + 4);
#pragma unroll
    for (int i = 0; i < 8; i++) {
        int r = ty * 8 + i;
        int s = ssrc[r], d = sdst[r];
        const float* xlp = g_xl + (size_t)s * HID + tx * 8;
        const float* xrp = g_xr + (size_t)d * HID + tx * 8;
        float4 xl0 = *(const float4*)(xlp);
        float4 xl1 = *(const float4*)(xlp + 4);
        float4 xr0 = *(const float4*)(xrp);
        float4 xr1 = *(const float4*)(xrp + 4);
        float2 v0 = up2(acc2[i][0]);
        float2 v1 = up2(acc2[i][1]);
        float2 v2 = up2(acc2[i][2]);
        float2 v3 = up2(acc2[i][3]);
        float p = lk(xl0.x + xr0.x + v0.x) * at0.x
                + lk(xl0.y + xr0.y + v0.y) * at0.y
                + lk(xl0.z + xr0.z + v1.x) * at0.z
                + lk(xl0.w + xr0.w + v1.y) * at0.w
                + lk(xl1.x + xr1.x + v2.x) * at1.x
                + lk(xl1.y + xr1.y + v2.y) * at1.y
                + lk(xl1.z + xr1.z + v3.x) * at1.z
                + lk(xl1.w + xr1.w + v3.y) * at1.w;
        sp[r][tx] = p;
    }
    __syncthreads();

    // Reduce 16 partials per row -> ez; denominator atomic
    if (tid < 128) {
        float sum = 0.f;
#pragma unroll
        for (int j = 0; j < 16; j++) sum += sp[tid][j];
        float ez = __expf(sum);
        sez[tid] = ez;
        int e = e0 + tid;
        if (e < T) red1(&g_denom[sdst[tid]], ez);
    }
    __syncthreads();

    // Epilogue 2: numerator atomics (xl reload is an L1/L2 hit)
#pragma unroll
    for (int i = 0; i < 8; i++) {
        int r = ty * 8 + i;
        int e = e0 + r;
        if (e >= T) continue;
        int s = ssrc[r], d = sdst[r];
        float ez = sez[r];
        const float* xlp = g_xl + (size_t)s * HID + tx * 8;
        float4 xl0 = *(const float4*)(xlp);
        float4 xl1 = *(const float4*)(xlp + 4);
        float* ap = g_acc + (size_t)d * HID + tx * 8;
        red4(ap,     ez * xl0.x, ez * xl0.y, ez * xl0.z, ez * xl0.w);
        red4(ap + 4, ez * xl1.x, ez * xl1.y, ez * xl1.z, ez * xl1.w);
    }
}

// ---------------- normalize + bias + silu ----------------
__global__ void k_norm(const float* __restrict__ bo, float* __restrict__ out, int N) {
    int i = blockIdx.x * blockDim.x + threadIdx.x;   // over N*32 float4s
    if (i >= N * 32) return;
    int node = i >> 5;
    int c = (i & 31) * 4;
    float inv = 1.0f / g_denom[node];
    float4 a = *(float4*)(g_acc + (size_t)node * HID + c);
    float4 b = *(const float4*)(bo + c);
    float vx = a.x * inv + b.x;
    float vy = a.y * inv + b.y;
    float vz = a.z * inv + b.z;
    float vw = a.w * inv + b.w;
    float4 o;
    o.x = vx / (1.0f + __expf(-vx));
    o.y = vy / (1.0f + __expf(-vy));
    o.z = vz / (1.0f + __expf(-vz));
    o.w = vw / (1.0f + __expf(-vw));
    *(float4*)(out + (size_t)node * HID + c) = o;
}

// ---------------- host orchestration ----------------
extern "C" void kernel_launch(void* const* d_in, const int* in_sizes, int n_in,
                              void* d_out, int out_size) {
    const float* x    = (const float*)d_in[0];
    const void*  eidx = d_in[1];
    const float* ea   = (const float*)d_in[2];
    const float* W_emb = (const float*)d_in[3];
    const float* b_emb = (const float*)d_in[4];
    const float* Wl[2]  = {(const float*)d_in[5],  (const float*)d_in[11]};
    const float* bl[2]  = {(const float*)d_in[6],  (const float*)d_in[12]};
    const float* Wr[2]  = {(const float*)d_in[7],  (const float*)d_in[13]};
    const float* We[2]  = {(const float*)d_in[8],  (const float*)d_in[14]};
    const float* att[2] = {(const float*)d_in[9],  (const float*)d_in[15]};
    const float* bo[2]  = {(const float*)d_in[10], (const float*)d_in[16]};

    int N = in_sizes[0] / HID;
    int E = in_sizes[2] / 32;
    int T = E + N;

    float *p_h;
    cudaGetSymbolAddress((void**)&p_h, g_h);

    int gb_n = (N + 127) / 128;

    // launch order puts the embedding GEMM at position 4 (profiled launch)
    k_detect<<<1, 1>>>(eidx, E, N);                                  // 1
    k_prep<<<(E + 255) / 256, 256>>>(eidx, E);                       // 2
    k_zero_dl<<<(N * 8 + 255) / 256, 256>>>(N);                      // 3
    k_gemm_tc<<<gb_n, 256>>>(x, W_emb, b_emb, p_h, N);               // 4 <- profiled
    k_loopacc<<<(E * 8 + 255) / 256, 256>>>(ea, E);                  // 5
    k_loopnorm<<<(N * 8 + 255) / 256, 256>>>(N);                     // 6

    float *p_xl, *p_xr;
    cudaGetSymbolAddress((void**)&p_xl, g_xl);
    cudaGetSymbolAddress((void**)&p_xr, g_xr);

    int eb = (T + 127) / 128;
    for (int l = 0; l < 2; l++) {
        k_gemm_tc<<<gb_n, 256>>>(p_h, Wl[l], bl[l], p_xl, N);
        k_gemm_tc<<<gb_n, 256>>>(p_h, Wr[l], nullptr, p_xr, N);
        k_zero_ad<<<(N * 32 + 255) / 256, 256>>>(N);
        k_escore<<<eb, 256>>>(ea, We[l], att[l], E, T);
        float* dst = (l == 0) ? p_h : (float*)d_out;
        k_norm<<<(N * 32 + 255) / 256, 256>>>(bo[l], dst, N);
    }
}